// round 7
// baseline (speedup 1.0000x reference)
#include <cuda_runtime.h>
#include <math.h>

#define BB  128   // batch
#define TT  256   // time steps
#define TD  256   // feature dim D
#define NS  32    // stack depth

// ---------------------------------------------------------------------------
// Device scratch (no allocations allowed)
// ---------------------------------------------------------------------------
__device__ float      g_scratch[BB * TT];           // latch gates g[b][t]
__device__ float      pop_scratch[BB * TT];         // pop[b][t]
__device__ float      latch_buf[BB * TT * TD];      // latch AFTER step t
__device__ ulonglong2 coef2_buf[BB * TT * NS * 2];  // [{a,a,e,e},{c,c,w,w}]

// f32x2 packed helpers (Blackwell FFMA2 only reachable via PTX)
#define FMA2(d, a, b, c) \
    asm("fma.rn.f32x2 %0, %1, %2, %3;" : "=l"(d) : "l"(a), "l"(b), "l"(c))
#define PACK2(d, lo, hi) \
    asm("mov.b64 %0, {%1, %2};" : "=l"(d) : "f"(lo), "f"(hi))
#define UNPACK2(lo, hi, s) \
    asm("mov.b64 {%0, %1}, %2;" : "=f"(lo), "=f"(hi) : "l"(s))

// ---------------------------------------------------------------------------
// K1: g[b][t] = elu(cos_sim(latch_enable, x[b,t,:])). One warp per (b,t).
// ---------------------------------------------------------------------------
__global__ void __launch_bounds__(256) precompute_g_kernel(
    const float* __restrict__ x,
    const float* __restrict__ le)
{
    const int warp = threadIdx.x >> 5;
    const int lane = threadIdx.x & 31;
    const int bt   = blockIdx.x * 8 + warp;
    const float* xp = x + (size_t)bt * TD;

    float dot = 0.f, nx = 0.f, nl = 0.f;
#pragma unroll
    for (int k = 0; k < 8; k++) {
        float xv = xp[lane + k * 32];
        float lv = le[lane + k * 32];
        dot = fmaf(lv, xv, dot);
        nx  = fmaf(xv, xv, nx);
        nl  = fmaf(lv, lv, nl);
    }
#pragma unroll
    for (int o = 16; o; o >>= 1) {
        dot += __shfl_xor_sync(0xffffffffu, dot, o);
        nx  += __shfl_xor_sync(0xffffffffu, nx,  o);
        nl  += __shfl_xor_sync(0xffffffffu, nl,  o);
    }
    if (lane == 0) {
        float an = fmaxf(sqrtf(nl), 1e-8f);
        float bn = fmaxf(sqrtf(nx), 1e-8f);
        float c  = dot / (an * bn);
        g_scratch[bt] = (c > 0.f) ? c : expm1f(c);
    }
}

// ---------------------------------------------------------------------------
// K2a: latch materialization. Thread = (b,d); scalar-coef linear scan over t.
// Loads are t-indexed (independent of the carried value) -> unroll gives MLP.
// ---------------------------------------------------------------------------
__global__ void __launch_bounds__(256) latch_scan_kernel(
    const float* __restrict__ x,
    const float* __restrict__ latch_init)
{
    const int b = blockIdx.x;
    const int d = threadIdx.x;

    float lat = latch_init[b * TD + d];
    const float* xb = x + (size_t)b * TT * TD + d;
    float*       lb = latch_buf + (size_t)b * TT * TD + d;
    const float* gb = g_scratch + b * TT;

#pragma unroll 8
    for (int t = 0; t < TT; t++) {
        float xv = __ldg(xb + (size_t)t * TD);
        float gg = __ldg(gb + t);
        lat = fmaf(gg, xv - lat, lat);       // = g*x + (1-g)*lat
        lb[(size_t)t * TD] = lat;
    }
}

// ---------------------------------------------------------------------------
// K2b: pop[b][t] = elu(cos_sim(should_pop, latch at step t-1)). Warp per (b,t).
// t=0 uses latch_init.
// ---------------------------------------------------------------------------
__global__ void __launch_bounds__(256) pop_kernel(
    const float* __restrict__ should_pop,
    const float* __restrict__ latch_init)
{
    const int warp = threadIdx.x >> 5;
    const int lane = threadIdx.x & 31;
    const int bt   = blockIdx.x * 8 + warp;
    const int b    = bt >> 8;          // TT = 256
    const int t    = bt & 255;

    const float* lp = (t == 0) ? (latch_init + (size_t)b * TD)
                               : (latch_buf + (size_t)(bt - 1) * TD);

    float dot = 0.f, nl = 0.f, ns = 0.f;
#pragma unroll
    for (int k = 0; k < 8; k++) {
        float lv = lp[lane + k * 32];
        float sv = should_pop[lane + k * 32];
        dot = fmaf(sv, lv, dot);
        nl  = fmaf(lv, lv, nl);
        ns  = fmaf(sv, sv, ns);
    }
#pragma unroll
    for (int o = 16; o; o >>= 1) {
        dot += __shfl_xor_sync(0xffffffffu, dot, o);
        nl  += __shfl_xor_sync(0xffffffffu, nl,  o);
        ns  += __shfl_xor_sync(0xffffffffu, ns,  o);
    }
    if (lane == 0) {
        float an = fmaxf(sqrtf(ns), 1e-8f);
        float bn = fmaxf(sqrtf(nl), 1e-8f);
        float c  = dot / (an * bn);
        pop_scratch[bt] = (c > 0.f) ? c : expm1f(c);
    }
}

// ---------------------------------------------------------------------------
// K2c: pointer scan. One warp per batch; pop precomputed, latch gone.
// Lane n owns unnormalized pointer slot Q[n]. Per-step chain:
// sigma butterfly || (roll shfl + log2) -> exp2. Coef store deferred 1 step
// (w needs next sigma). Coefs written pre-duplicated for K3's f32x2 path.
// ---------------------------------------------------------------------------
__global__ void __launch_bounds__(32) pointer_scan_kernel(
    const float* __restrict__ sharpen_ptr)
{
    const int b    = blockIdx.x;
    const int lane = threadIdx.x;
    const unsigned FULL = 0xffffffffu;

    const float s5 = sharpen_ptr[0];

    float Q = (lane == 0) ? 1.0f : 1e-6f;   // raw initial pointer

    const float* pb = pop_scratch + b * TT;
    float4* cb = (float4*)(coef2_buf + (size_t)b * TT * NS * 2);

    float popPrev = 0.f, aPrev = 0.f, ePrev = 0.f, cPrev = 0.f;

#pragma unroll 2
    for (int t = 0; t < TT; t++) {
        const float pop  = __ldg(pb + t);
        const float push = 1.0f - pop;

        // sigma = sum(Q) (butterfly; overlaps the roll/log2 below)
        float sig = Q;
        float Qp = __shfl_sync(FULL, Q, (lane + 31) & 31);  // p_push source
        sig += __shfl_xor_sync(FULL, sig, 1);
        float Qm = __shfl_sync(FULL, Q, (lane + 1) & 31);   // p_pop source
        sig += __shfl_xor_sync(FULL, sig, 2);
        float np = fmaf(push, Qp, pop * Qm);                // unnormalized new ptr
        sig += __shfl_xor_sync(FULL, sig, 4);
        float lnp = __log2f(np);
        sig += __shfl_xor_sync(FULL, sig, 8);
        sig += __shfl_xor_sync(FULL, sig, 16);

        float invs = 1.0f / sig;
        float lgs  = __log2f(sig);

        // deferred store for step t-1: w_{t-1} = pop_{t-1} * Q_t / sigma_t
        if (t > 0) {
            float w = popPrev * Q * invs;
            cb[((t - 1) * NS + lane) * 2]     = make_float4(aPrev, aPrev, ePrev, ePrev);
            cb[((t - 1) * NS + lane) * 2 + 1] = make_float4(cPrev, cPrev, w, w);
        }

        // coefs for step t from normalized old pointer
        float e = push * (Qp * invs);
        float f = pop  * (Q  * invs);
        float a = 1.0f - e - f;
        float c = 1e-6f * f;

        // sharpened next pointer: (np/sigma)^s  (underflow -> 0, same as ref fp32)
        float Qn = (np > 0.f) ? exp2f(s5 * (lnp - lgs)) : 0.f;

        Q = Qn;
        popPrev = pop; aPrev = a; ePrev = e; cPrev = c;
    }

    // final store for t = 255
    {
        float sig = Q;
#pragma unroll
        for (int o = 16; o; o >>= 1) sig += __shfl_xor_sync(FULL, sig, o);
        float invs = 1.0f / fmaxf(sig, 1e-8f);
        float w = popPrev * Q * invs;
        cb[((TT - 1) * NS + lane) * 2]     = make_float4(aPrev, aPrev, ePrev, ePrev);
        cb[((TT - 1) * NS + lane) * 2 + 1] = make_float4(cPrev, cPrev, w, w);
    }
}

// ---------------------------------------------------------------------------
// K3: stack recurrence, packed f32x2. Thread = (b, columns 2i and 2i+1).
// Per slot per step: 2x LDG.128 (pre-duplicated coefs) + 3x FFMA2.
// No barriers, no shuffles, no cross-thread anything.
// ---------------------------------------------------------------------------
__global__ void __launch_bounds__(128) stack_kernel(
    const float* __restrict__ x,
    float* __restrict__ out)
{
    const int b = blockIdx.x;
    const int i = threadIdx.x;

    const float2* xb2 = (const float2*)(x + (size_t)b * TT * TD);
    float2*       ob2 = (float2*)(out + (size_t)b * TT * TD);
    const ulonglong2* cb = coef2_buf + (size_t)b * TT * NS * 2;

    unsigned long long st2[NS];
    {
        unsigned long long init;
        PACK2(init, 1e-6f, 1e-6f);
#pragma unroll
        for (int n = 0; n < NS; n++) st2[n] = init;
    }

    for (int t = 0; t < TT; t++) {
        float2 xv = __ldg(&xb2[t * (TD / 2) + i]);
        unsigned long long in2, s2;
        PACK2(in2, xv.x, xv.y);
        PACK2(s2, 0.0f, 0.0f);

        const ulonglong2* ct = cb + (size_t)t * NS * 2;
#pragma unroll
        for (int n = 0; n < NS; n++) {
            ulonglong2 A = __ldg(&ct[n * 2]);       // {a,a | e,e}
            ulonglong2 B = __ldg(&ct[n * 2 + 1]);   // {c,c | w,w}
            unsigned long long z2, v2;
            FMA2(z2, A.y, in2, B.x);    // e*in + c
            FMA2(v2, A.x, st2[n], z2);  // a*st + z
            st2[n] = v2;
            FMA2(s2, v2, B.y, s2);      // s += v*w
        }
        float lo, hi;
        UNPACK2(lo, hi, s2);
        ob2[t * (TD / 2) + i] = make_float2(lo, hi);
    }
}

// ---------------------------------------------------------------------------
// metadata order: x[B*T*D], should_pop[D], sharpen_pointer[1],
//                 latch_enable[D], latch_init[B*D]  -> out[B*T*D] float32
// ---------------------------------------------------------------------------
extern "C" void kernel_launch(void* const* d_in, const int* in_sizes, int n_in,
                              void* d_out, int out_size)
{
    const float* x   = (const float*)d_in[0];
    const float* sp  = (const float*)d_in[1];
    const float* shp = (const float*)d_in[2];
    const float* le  = (const float*)d_in[3];
    const float* li  = (const float*)d_in[4];
    float* out = (float*)d_out;

    precompute_g_kernel<<<(BB * TT) / 8, 256>>>(x, le);
    latch_scan_kernel<<<BB, TD>>>(x, li);
    pop_kernel<<<(BB * TT) / 8, 256>>>(sp, li);
    pointer_scan_kernel<<<BB, 32>>>(shp);
    stack_kernel<<<BB, 128>>>(x, out);
}

// round 8
// speedup vs baseline: 2.0975x; 2.0975x over previous
#include <cuda_runtime.h>
#include <math.h>

#define BB  128   // batch
#define TT  256   // time steps
#define TD  256   // feature dim D
#define NS  32    // stack depth

// ---------------------------------------------------------------------------
// Device scratch (no allocations allowed)
// ---------------------------------------------------------------------------
__device__ float  g_scratch[BB * TT];        // latch gates g[b][t]
__device__ float  pop_scratch[BB * TT];      // pop[b][t]
__device__ float  latch_buf[BB * TT * TD];   // latch AFTER step t
__device__ float4 coef_buf[BB * TT * NS];    // {a, e, c, w} per (b,t,slot)

// ---------------------------------------------------------------------------
// K1: g[b][t] = elu(cos_sim(latch_enable, x[b,t,:])). One warp per (b,t).
// ---------------------------------------------------------------------------
__global__ void __launch_bounds__(256) precompute_g_kernel(
    const float* __restrict__ x,
    const float* __restrict__ le)
{
    const int warp = threadIdx.x >> 5;
    const int lane = threadIdx.x & 31;
    const int bt   = blockIdx.x * 8 + warp;
    const float* xp = x + (size_t)bt * TD;

    float dot = 0.f, nx = 0.f, nl = 0.f;
#pragma unroll
    for (int k = 0; k < 8; k++) {
        float xv = xp[lane + k * 32];
        float lv = le[lane + k * 32];
        dot = fmaf(lv, xv, dot);
        nx  = fmaf(xv, xv, nx);
        nl  = fmaf(lv, lv, nl);
    }
#pragma unroll
    for (int o = 16; o; o >>= 1) {
        dot += __shfl_xor_sync(0xffffffffu, dot, o);
        nx  += __shfl_xor_sync(0xffffffffu, nx,  o);
        nl  += __shfl_xor_sync(0xffffffffu, nl,  o);
    }
    if (lane == 0) {
        float an = fmaxf(sqrtf(nl), 1e-8f);
        float bn = fmaxf(sqrtf(nx), 1e-8f);
        float c  = dot / (an * bn);
        g_scratch[bt] = (c > 0.f) ? c : expm1f(c);
    }
}

// ---------------------------------------------------------------------------
// K2a: latch materialization. Thread = (b,d); scalar-coef linear scan over t.
// Loads are t-indexed (independent of carried value) -> unroll gives MLP.
// ---------------------------------------------------------------------------
__global__ void __launch_bounds__(256) latch_scan_kernel(
    const float* __restrict__ x,
    const float* __restrict__ latch_init)
{
    const int b = blockIdx.x;
    const int d = threadIdx.x;

    float lat = latch_init[b * TD + d];
    const float* xb = x + (size_t)b * TT * TD + d;
    float*       lb = latch_buf + (size_t)b * TT * TD + d;
    const float* gb = g_scratch + b * TT;

#pragma unroll 8
    for (int t = 0; t < TT; t++) {
        float xv = __ldg(xb + (size_t)t * TD);
        float gg = __ldg(gb + t);
        lat = fmaf(gg, xv - lat, lat);       // = g*x + (1-g)*lat
        lb[(size_t)t * TD] = lat;
    }
}

// ---------------------------------------------------------------------------
// K2b: pop[b][t] = elu(cos_sim(should_pop, latch at step t-1)). Warp per (b,t).
// t=0 uses latch_init.
// ---------------------------------------------------------------------------
__global__ void __launch_bounds__(256) pop_kernel(
    const float* __restrict__ should_pop,
    const float* __restrict__ latch_init)
{
    const int warp = threadIdx.x >> 5;
    const int lane = threadIdx.x & 31;
    const int bt   = blockIdx.x * 8 + warp;
    const int b    = bt >> 8;          // TT = 256
    const int t    = bt & 255;

    const float* lp = (t == 0) ? (latch_init + (size_t)b * TD)
                               : (latch_buf + (size_t)(bt - 1) * TD);

    float dot = 0.f, nl = 0.f, ns = 0.f;
#pragma unroll
    for (int k = 0; k < 8; k++) {
        float lv = lp[lane + k * 32];
        float sv = should_pop[lane + k * 32];
        dot = fmaf(sv, lv, dot);
        nl  = fmaf(lv, lv, nl);
        ns  = fmaf(sv, sv, ns);
    }
#pragma unroll
    for (int o = 16; o; o >>= 1) {
        dot += __shfl_xor_sync(0xffffffffu, dot, o);
        nl  += __shfl_xor_sync(0xffffffffu, nl,  o);
        ns  += __shfl_xor_sync(0xffffffffu, ns,  o);
    }
    if (lane == 0) {
        float an = fmaxf(sqrtf(ns), 1e-8f);
        float bn = fmaxf(sqrtf(nl), 1e-8f);
        float c  = dot / (an * bn);
        pop_scratch[bt] = (c > 0.f) ? c : expm1f(c);
    }
}

// ---------------------------------------------------------------------------
// K2c: pointer scan. One warp per batch; pop precomputed, latch gone.
// Lane n owns unnormalized pointer slot Q[n]. Sigma butterfly interleaved
// with the roll/log2 chain; coef store deferred 1 step (w needs next sigma).
// ---------------------------------------------------------------------------
__global__ void __launch_bounds__(32) pointer_scan_kernel(
    const float* __restrict__ sharpen_ptr)
{
    const int b    = blockIdx.x;
    const int lane = threadIdx.x;
    const unsigned FULL = 0xffffffffu;

    const float s5 = sharpen_ptr[0];

    float Q = (lane == 0) ? 1.0f : 1e-6f;   // raw initial pointer

    const float* pb = pop_scratch + b * TT;
    float4*      cb = coef_buf + (size_t)b * TT * NS;

    float popPrev = 0.f, aPrev = 0.f, ePrev = 0.f, cPrev = 0.f;

#pragma unroll 2
    for (int t = 0; t < TT; t++) {
        const float pop  = __ldg(pb + t);
        const float push = 1.0f - pop;

        // sigma = sum(Q) (butterfly; overlaps the roll/log2 below)
        float sig = Q;
        float Qp = __shfl_sync(FULL, Q, (lane + 31) & 31);  // p_push source
        sig += __shfl_xor_sync(FULL, sig, 1);
        float Qm = __shfl_sync(FULL, Q, (lane + 1) & 31);   // p_pop source
        sig += __shfl_xor_sync(FULL, sig, 2);
        float np = fmaf(push, Qp, pop * Qm);                // unnormalized new ptr
        sig += __shfl_xor_sync(FULL, sig, 4);
        float lnp = __log2f(np);
        sig += __shfl_xor_sync(FULL, sig, 8);
        sig += __shfl_xor_sync(FULL, sig, 16);

        float invs = 1.0f / sig;
        float lgs  = __log2f(sig);

        // deferred store for step t-1: w_{t-1} = pop_{t-1} * Q_t / sigma_t
        if (t > 0) {
            float w = popPrev * Q * invs;
            cb[(t - 1) * NS + lane] = make_float4(aPrev, ePrev, cPrev, w);
        }

        // coefs for step t from normalized old pointer
        float e = push * (Qp * invs);
        float f = pop  * (Q  * invs);
        float a = 1.0f - e - f;
        float c = 1e-6f * f;

        // sharpened next pointer: (np/sigma)^s  (underflow -> 0, as ref fp32)
        float Qn = (np > 0.f) ? exp2f(s5 * (lnp - lgs)) : 0.f;

        Q = Qn;
        popPrev = pop; aPrev = a; ePrev = e; cPrev = c;
    }

    // final store for t = 255
    {
        float sig = Q;
#pragma unroll
        for (int o = 16; o; o >>= 1) sig += __shfl_xor_sync(FULL, sig, o);
        float invs = 1.0f / fmaxf(sig, 1e-8f);
        float w = popPrev * Q * invs;
        cb[(TT - 1) * NS + lane] = make_float4(aPrev, ePrev, cPrev, w);
    }
}

// ---------------------------------------------------------------------------
// K3: stack recurrence, scalar FMA (register-friendly). Thread = (b, cols
// i and i+128). Per step: 32 broadcast LDG.128 coef + 2 x-loads + 96 FMA.
// No barriers, no shuffles, no cross-thread communication.
// ---------------------------------------------------------------------------
__global__ void __launch_bounds__(128) stack_kernel(
    const float* __restrict__ x,
    float* __restrict__ out)
{
    const int b = blockIdx.x;
    const int i = threadIdx.x;

    const float4* cb = coef_buf + (size_t)b * TT * NS;
    const float*  xb = x   + (size_t)b * TT * TD;
    float*        ob = out + (size_t)b * TT * TD;

    float st0[NS], st1[NS];
#pragma unroll
    for (int n = 0; n < NS; n++) { st0[n] = 1e-6f; st1[n] = 1e-6f; }

    for (int t = 0; t < TT; t++) {
        const float in0 = __ldg(&xb[t * TD + i]);
        const float in1 = __ldg(&xb[t * TD + i + 128]);
        const float4* cf = cb + t * NS;
        float s0 = 0.f, s1 = 0.f;
#pragma unroll
        for (int n = 0; n < NS; n++) {
            float4 k = __ldg(&cf[n]);
            float z0 = fmaf(k.y, in0, k.z);
            float z1 = fmaf(k.y, in1, k.z);
            float v0 = fmaf(k.x, st0[n], z0);
            float v1 = fmaf(k.x, st1[n], z1);
            st0[n] = v0; st1[n] = v1;
            s0 = fmaf(v0, k.w, s0);
            s1 = fmaf(v1, k.w, s1);
        }
        ob[t * TD + i]       = s0;
        ob[t * TD + i + 128] = s1;
    }
}

// ---------------------------------------------------------------------------
// metadata order: x[B*T*D], should_pop[D], sharpen_pointer[1],
//                 latch_enable[D], latch_init[B*D]  -> out[B*T*D] float32
// ---------------------------------------------------------------------------
extern "C" void kernel_launch(void* const* d_in, const int* in_sizes, int n_in,
                              void* d_out, int out_size)
{
    const float* x   = (const float*)d_in[0];
    const float* sp  = (const float*)d_in[1];
    const float* shp = (const float*)d_in[2];
    const float* le  = (const float*)d_in[3];
    const float* li  = (const float*)d_in[4];
    float* out = (float*)d_out;

    precompute_g_kernel<<<(BB * TT) / 8, 256>>>(x, le);
    latch_scan_kernel<<<BB, TD>>>(x, li);
    pop_kernel<<<(BB * TT) / 8, 256>>>(sp, li);
    pointer_scan_kernel<<<BB, 32>>>(shp);
    stack_kernel<<<BB, 128>>>(x, out);
}

// round 9
// speedup vs baseline: 4.1693x; 1.9877x over previous
#include <cuda_runtime.h>
#include <math.h>
#include <stdint.h>

#define BB  128   // batch
#define TT  256   // time steps
#define TD  256   // feature dim D
#define NS  32    // stack depth

// ---------------------------------------------------------------------------
// Device scratch (no allocations allowed)
// ---------------------------------------------------------------------------
__device__ float  g_scratch[BB * TT];        // latch gates g[b][t]
__device__ float  pop_scratch[BB * TT];      // pop[b][t]
__device__ float  latch_buf[BB * TT * TD];   // latch AFTER step t
__device__ float4 coef_buf[BB * TT * NS];    // {a, e, c, w} per (b,t,slot)

__device__ __forceinline__ float ex2f(float v) {
    float r; asm("ex2.approx.f32 %0, %1;" : "=f"(r) : "f"(v)); return r;
}
__device__ __forceinline__ void cp16(uint32_t saddr, const void* gaddr) {
    asm volatile("cp.async.cg.shared.global [%0], [%1], 16;"
                 :: "r"(saddr), "l"(gaddr));
}
#define CP_COMMIT() asm volatile("cp.async.commit_group;")
#define CP_WAIT2()  asm volatile("cp.async.wait_group 2;")

// ---------------------------------------------------------------------------
// K1: g[b][t] = elu(cos_sim(latch_enable, x[b,t,:])). One warp per (b,t).
// ---------------------------------------------------------------------------
__global__ void __launch_bounds__(256) precompute_g_kernel(
    const float* __restrict__ x,
    const float* __restrict__ le)
{
    const int warp = threadIdx.x >> 5;
    const int lane = threadIdx.x & 31;
    const int bt   = blockIdx.x * 8 + warp;
    const float* xp = x + (size_t)bt * TD;

    float dot = 0.f, nx = 0.f, nl = 0.f;
#pragma unroll
    for (int k = 0; k < 8; k++) {
        float xv = xp[lane + k * 32];
        float lv = le[lane + k * 32];
        dot = fmaf(lv, xv, dot);
        nx  = fmaf(xv, xv, nx);
        nl  = fmaf(lv, lv, nl);
    }
#pragma unroll
    for (int o = 16; o; o >>= 1) {
        dot += __shfl_xor_sync(0xffffffffu, dot, o);
        nx  += __shfl_xor_sync(0xffffffffu, nx,  o);
        nl  += __shfl_xor_sync(0xffffffffu, nl,  o);
    }
    if (lane == 0) {
        float an = fmaxf(sqrtf(nl), 1e-8f);
        float bn = fmaxf(sqrtf(nx), 1e-8f);
        float c  = dot / (an * bn);
        g_scratch[bt] = (c > 0.f) ? c : expm1f(c);
    }
}

// ---------------------------------------------------------------------------
// K2a: latch materialization. Thread = (b,d); scalar-coef linear scan over t.
// ---------------------------------------------------------------------------
__global__ void __launch_bounds__(256) latch_scan_kernel(
    const float* __restrict__ x,
    const float* __restrict__ latch_init)
{
    const int b = blockIdx.x;
    const int d = threadIdx.x;

    float lat = latch_init[b * TD + d];
    const float* xb = x + (size_t)b * TT * TD + d;
    float*       lb = latch_buf + (size_t)b * TT * TD + d;
    const float* gb = g_scratch + b * TT;

#pragma unroll 8
    for (int t = 0; t < TT; t++) {
        float xv = __ldg(xb + (size_t)t * TD);
        float gg = __ldg(gb + t);
        lat = fmaf(gg, xv - lat, lat);       // = g*x + (1-g)*lat
        lb[(size_t)t * TD] = lat;
    }
}

// ---------------------------------------------------------------------------
// K2b: pop[b][t] = elu(cos_sim(should_pop, latch at step t-1)). Warp per (b,t).
// ---------------------------------------------------------------------------
__global__ void __launch_bounds__(256) pop_kernel(
    const float* __restrict__ should_pop,
    const float* __restrict__ latch_init)
{
    const int warp = threadIdx.x >> 5;
    const int lane = threadIdx.x & 31;
    const int bt   = blockIdx.x * 8 + warp;
    const int b    = bt >> 8;          // TT = 256
    const int t    = bt & 255;

    const float* lp = (t == 0) ? (latch_init + (size_t)b * TD)
                               : (latch_buf + (size_t)(bt - 1) * TD);

    float dot = 0.f, nl = 0.f, ns = 0.f;
#pragma unroll
    for (int k = 0; k < 8; k++) {
        float lv = lp[lane + k * 32];
        float sv = should_pop[lane + k * 32];
        dot = fmaf(sv, lv, dot);
        nl  = fmaf(lv, lv, nl);
        ns  = fmaf(sv, sv, ns);
    }
#pragma unroll
    for (int o = 16; o; o >>= 1) {
        dot += __shfl_xor_sync(0xffffffffu, dot, o);
        nl  += __shfl_xor_sync(0xffffffffu, nl,  o);
        ns  += __shfl_xor_sync(0xffffffffu, ns,  o);
    }
    if (lane == 0) {
        float an = fmaxf(sqrtf(ns), 1e-8f);
        float bn = fmaxf(sqrtf(nl), 1e-8f);
        float c  = dot / (an * bn);
        pop_scratch[bt] = (c > 0.f) ? c : expm1f(c);
    }
}

// ---------------------------------------------------------------------------
// K2c: pointer scan. One warp per batch. Chain: roll-shfl + lg2 overlapped
// with sigma butterfly -> lg2(sigma) -> fma -> ex2.approx. Unroll 4 batches
// the pop loads ahead of the chain. Coef store deferred one step.
// ---------------------------------------------------------------------------
__global__ void __launch_bounds__(32) pointer_scan_kernel(
    const float* __restrict__ sharpen_ptr)
{
    const int b    = blockIdx.x;
    const int lane = threadIdx.x;
    const unsigned FULL = 0xffffffffu;

    const float s5 = sharpen_ptr[0];

    float Q = (lane == 0) ? 1.0f : 1e-6f;   // raw initial pointer

    const float* pb = pop_scratch + b * TT;
    float4*      cb = coef_buf + (size_t)b * TT * NS;

    float popPrev = 0.f, aPrev = 0.f, ePrev = 0.f, cPrev = 0.f;

#pragma unroll 4
    for (int t = 0; t < TT; t++) {
        const float pop  = __ldg(pb + t);
        const float push = 1.0f - pop;

        // sigma = sum(Q) (butterfly; overlaps the roll/lg2 below)
        float sig = Q;
        float Qp = __shfl_sync(FULL, Q, (lane + 31) & 31);  // p_push source
        sig += __shfl_xor_sync(FULL, sig, 1);
        float Qm = __shfl_sync(FULL, Q, (lane + 1) & 31);   // p_pop source
        sig += __shfl_xor_sync(FULL, sig, 2);
        float np = fmaf(push, Qp, pop * Qm);                // unnormalized new ptr
        sig += __shfl_xor_sync(FULL, sig, 4);
        float lnp = __log2f(np);
        sig += __shfl_xor_sync(FULL, sig, 8);
        sig += __shfl_xor_sync(FULL, sig, 16);

        float invs = 1.0f / sig;
        float lgs  = __log2f(sig);

        // deferred store for step t-1: w_{t-1} = pop_{t-1} * Q_t / sigma_t
        if (t > 0) {
            float w = popPrev * Q * invs;
            cb[(t - 1) * NS + lane] = make_float4(aPrev, ePrev, cPrev, w);
        }

        // coefs for step t from normalized old pointer
        float e = push * (Qp * invs);
        float f = pop  * (Q  * invs);
        float a = 1.0f - e - f;
        float c = 1e-6f * f;

        // sharpened next pointer: (np/sigma)^s via MUFU lg2/ex2
        float Qn = (np > 0.f) ? ex2f(s5 * (lnp - lgs)) : 0.f;

        Q = Qn;
        popPrev = pop; aPrev = a; ePrev = e; cPrev = c;
    }

    // final store for t = 255
    {
        float sig = Q;
#pragma unroll
        for (int o = 16; o; o >>= 1) sig += __shfl_xor_sync(FULL, sig, o);
        float invs = 1.0f / fmaxf(sig, 1e-8f);
        float w = popPrev * Q * invs;
        cb[(TT - 1) * NS + lane] = make_float4(aPrev, ePrev, cPrev, w);
    }
}

// ---------------------------------------------------------------------------
// K3: stack recurrence. 256 threads (8 warps/SM), thread = (b, column d),
// st[32] in registers. Coefs staged into a 4-slot smem ring by warp 0 via
// cp.async, prefetched 3 steps ahead; consumers read broadcast LDS.128.
// One __syncthreads per step (after compute -> no ring-slot race).
// ---------------------------------------------------------------------------
__global__ void __launch_bounds__(256) stack_kernel(
    const float* __restrict__ x,
    float* __restrict__ out)
{
    __shared__ float4 cbuf[4][NS];     // 2 KB ring

    const int b = blockIdx.x;
    const int d = threadIdx.x;

    const float4* cb = coef_buf + (size_t)b * TT * NS;
    const float*  xb = x   + (size_t)b * TT * TD + d;
    float*        ob = out + (size_t)b * TT * TD + d;

    float st[NS];
#pragma unroll
    for (int n = 0; n < NS; n++) st[n] = 1e-6f;

    // prologue: stages 0..2 in flight
    if (d < NS) {
        uint32_t s0 = (uint32_t)__cvta_generic_to_shared(&cbuf[0][d]);
        cp16(s0,                    &cb[0 * NS + d]); CP_COMMIT();
        cp16(s0 + 1 * NS * 16,      &cb[1 * NS + d]); CP_COMMIT();
        cp16(s0 + 2 * NS * 16,      &cb[2 * NS + d]); CP_COMMIT();
        CP_WAIT2();                 // stage 0 complete
    }
    __syncthreads();

    float xv = __ldg(xb);           // x for t = 0

    for (int t = 0; t < TT; t++) {
        // prefetch x for t+1 (off-chain)
        float xnext = (t + 1 < TT) ? __ldg(xb + (size_t)(t + 1) * TD) : 0.f;

        const float4* cf = cbuf[t & 3];
        float s = 0.f;
#pragma unroll
        for (int n = 0; n < NS; n++) {
            float4 k = cf[n];
            float v = fmaf(k.x, st[n], fmaf(k.y, xv, k.z));
            st[n] = v;
            s = fmaf(v, k.w, s);
        }
        ob[(size_t)t * TD] = s;

        // issue stage t+3 (overwrites slot used at t-1; all threads passed
        // the barrier at end of t-1, so no race), then ensure t+1 complete.
        if (d < NS) {
            if (t + 3 < TT) {
                uint32_t sa = (uint32_t)__cvta_generic_to_shared(&cbuf[(t + 3) & 3][d]);
                cp16(sa, &cb[(t + 3) * NS + d]);
            }
            CP_COMMIT();            // keep one group per iteration (uniform)
            CP_WAIT2();             // stage t+1 complete
        }
        __syncthreads();
        xv = xnext;
    }
}

// ---------------------------------------------------------------------------
// metadata order: x[B*T*D], should_pop[D], sharpen_pointer[1],
//                 latch_enable[D], latch_init[B*D]  -> out[B*T*D] float32
// ---------------------------------------------------------------------------
extern "C" void kernel_launch(void* const* d_in, const int* in_sizes, int n_in,
                              void* d_out, int out_size)
{
    const float* x   = (const float*)d_in[0];
    const float* sp  = (const float*)d_in[1];
    const float* shp = (const float*)d_in[2];
    const float* le  = (const float*)d_in[3];
    const float* li  = (const float*)d_in[4];
    float* out = (float*)d_out;

    precompute_g_kernel<<<(BB * TT) / 8, 256>>>(x, le);
    latch_scan_kernel<<<BB, TD>>>(x, li);
    pop_kernel<<<(BB * TT) / 8, 256>>>(sp, li);
    pointer_scan_kernel<<<BB, 32>>>(shp);
    stack_kernel<<<BB, 256>>>(x, out);
}

// round 13
// speedup vs baseline: 4.4747x; 1.0732x over previous
#include <cuda_runtime.h>
#include <math.h>
#include <stdint.h>

#define BB  128   // batch
#define TT  256   // time steps
#define TD  256   // feature dim D
#define NS  32    // stack depth

// ---------------------------------------------------------------------------
// Device scratch (no allocations allowed)
// ---------------------------------------------------------------------------
__device__ float      g_scratch[BB * TT];          // latch gates g[b][t]
__device__ float      pop_scratch[BB * TT];        // pop[b][t]
__device__ ulonglong2 coef2_buf[BB * TT * NS * 2]; // {a,a,e,e},{c,c,w,w}

__device__ __forceinline__ float ex2f(float v) {
    float r; asm("ex2.approx.f32 %0, %1;" : "=f"(r) : "f"(v)); return r;
}
__device__ __forceinline__ void cp16(uint32_t saddr, const void* gaddr) {
    asm volatile("cp.async.cg.shared.global [%0], [%1], 16;"
                 :: "r"(saddr), "l"(gaddr));
}
#define CP_COMMIT() asm volatile("cp.async.commit_group;")
#define CP_WAIT2()  asm volatile("cp.async.wait_group 2;")

// f32x2 packed math (Blackwell FFMA2, PTX-only)
#define FMA2(d, a, b, c) \
    asm("fma.rn.f32x2 %0, %1, %2, %3;" : "=l"(d) : "l"(a), "l"(b), "l"(c))
#define PACK2(d, lo, hi) \
    asm("mov.b64 %0, {%1, %2};" : "=l"(d) : "f"(lo), "f"(hi))
#define UNPACK2(lo, hi, s) \
    asm("mov.b64 {%0, %1}, %2;" : "=f"(lo), "=f"(hi) : "l"(s))

// ---------------------------------------------------------------------------
// K1: g[b][t] = elu(cos_sim(latch_enable, x[b,t,:])). One warp per (b,t).
// ---------------------------------------------------------------------------
__global__ void __launch_bounds__(256) precompute_g_kernel(
    const float* __restrict__ x,
    const float* __restrict__ le)
{
    const int warp = threadIdx.x >> 5;
    const int lane = threadIdx.x & 31;
    const int bt   = blockIdx.x * 8 + warp;
    const float* xp = x + (size_t)bt * TD;

    float dot = 0.f, nx = 0.f, nl = 0.f;
#pragma unroll
    for (int k = 0; k < 8; k++) {
        float xv = xp[lane + k * 32];
        float lv = le[lane + k * 32];
        dot = fmaf(lv, xv, dot);
        nx  = fmaf(xv, xv, nx);
        nl  = fmaf(lv, lv, nl);
    }
#pragma unroll
    for (int o = 16; o; o >>= 1) {
        dot += __shfl_xor_sync(0xffffffffu, dot, o);
        nx  += __shfl_xor_sync(0xffffffffu, nx,  o);
        nl  += __shfl_xor_sync(0xffffffffu, nl,  o);
    }
    if (lane == 0) {
        float an = fmaxf(sqrtf(nl), 1e-8f);
        float bn = fmaxf(sqrtf(nx), 1e-8f);
        float c  = dot / (an * bn);
        g_scratch[bt] = (c > 0.f) ? c : expm1f(c);
    }
}

// ---------------------------------------------------------------------------
// K2ab: fused latch scan + pop reduction. One CTA per batch; thread d carries
// latch[d] in a register. Per step: warp butterfly of (sp.latch, latch^2)
// into a per-warp smem row (NO barrier in the loop; warps independent).
// One __syncthreads, then 256 threads finish one t each -> pop[b][t].
// Never materializes latch to global (saves 66 MB traffic vs split version).
// pop[t] uses latch BEFORE the step-t update (relay of 1) -> reduce first.
// ---------------------------------------------------------------------------
__global__ void __launch_bounds__(256) latch_pop_kernel(
    const float* __restrict__ x,
    const float* __restrict__ should_pop,
    const float* __restrict__ latch_init)
{
    __shared__ float2 part[8][TT];    // 16 KB: per-warp partials per t
    __shared__ float  spn[8];

    const int b    = blockIdx.x;
    const int d    = threadIdx.x;
    const int warp = d >> 5;
    const int lane = d & 31;

    const float sp = should_pop[d];
    float lat      = latch_init[b * TD + d];

    // |sp|^2 block reduction (once)
    {
        float r = sp * sp;
#pragma unroll
        for (int o = 16; o; o >>= 1) r += __shfl_xor_sync(0xffffffffu, r, o);
        if (lane == 0) spn[warp] = r;
    }
    __syncthreads();
    float sp2 = 0.f;
#pragma unroll
    for (int w = 0; w < 8; w++) sp2 += spn[w];
    const float inv_an = 1.0f / fmaxf(sqrtf(sp2), 1e-8f);

    const float* xb = x + (size_t)b * TT * TD + d;
    const float* gb = g_scratch + b * TT;

#pragma unroll 4
    for (int t = 0; t < TT; t++) {
        // reduce PRE-update latch (pop[t] depends on latch after step t-1)
        float q0 = sp * lat, q1 = lat * lat;
#pragma unroll
        for (int o = 16; o; o >>= 1) {
            q0 += __shfl_xor_sync(0xffffffffu, q0, o);
            q1 += __shfl_xor_sync(0xffffffffu, q1, o);
        }
        if (lane == 0) part[warp][t] = make_float2(q0, q1);

        // latch update (off the reduction path)
        float xv = __ldg(xb + (size_t)t * TD);
        float gg = __ldg(gb + t);
        lat = fmaf(gg, xv - lat, lat);
    }
    __syncthreads();

    // phase 2: thread t finishes pop[b][t]
    {
        const int t = d;
        float dot = 0.f, nl = 0.f;
#pragma unroll
        for (int w = 0; w < 8; w++) {
            float2 p = part[w][t];
            dot += p.x; nl += p.y;
        }
        float bn   = fmaxf(sqrtf(nl), 1e-8f);
        float cosv = dot * inv_an / bn;
        pop_scratch[b * TT + t] = (cosv > 0.f) ? cosv : expm1f(cosv);
    }
}

// ---------------------------------------------------------------------------
// K2c: pointer scan. One warp per batch. Sigma butterfly interleaved with the
// roll/lg2 chain; ex2.approx for the sharpen. Coef store deferred one step;
// coefs written pre-duplicated for K3's f32x2 path.
// ---------------------------------------------------------------------------
__global__ void __launch_bounds__(32) pointer_scan_kernel(
    const float* __restrict__ sharpen_ptr)
{
    const int b    = blockIdx.x;
    const int lane = threadIdx.x;
    const unsigned FULL = 0xffffffffu;

    const float s5 = sharpen_ptr[0];

    float Q = (lane == 0) ? 1.0f : 1e-6f;   // raw initial pointer

    const float* pb = pop_scratch + b * TT;
    float4*      cb = (float4*)(coef2_buf + (size_t)b * TT * NS * 2);

    float popPrev = 0.f, aPrev = 0.f, ePrev = 0.f, cPrev = 0.f;

#pragma unroll 4
    for (int t = 0; t < TT; t++) {
        const float pop  = __ldg(pb + t);
        const float push = 1.0f - pop;

        // sigma = sum(Q) butterfly, interleaved with the roll/lg2 chain
        float sig = Q;
        float Qp = __shfl_sync(FULL, Q, (lane + 31) & 31);  // p_push source
        sig += __shfl_xor_sync(FULL, sig, 1);
        float Qm = __shfl_sync(FULL, Q, (lane + 1) & 31);   // p_pop source
        sig += __shfl_xor_sync(FULL, sig, 2);
        float np = fmaf(push, Qp, pop * Qm);                // unnormalized new ptr
        sig += __shfl_xor_sync(FULL, sig, 4);
        float lnp = __log2f(np);
        sig += __shfl_xor_sync(FULL, sig, 8);
        sig += __shfl_xor_sync(FULL, sig, 16);

        float invs = 1.0f / sig;
        float lgs  = __log2f(sig);

        // deferred store for step t-1: w_{t-1} = pop_{t-1} * Q_t / sigma_t
        if (t > 0) {
            float w = popPrev * Q * invs;
            cb[((t - 1) * NS + lane) * 2]     = make_float4(aPrev, aPrev, ePrev, ePrev);
            cb[((t - 1) * NS + lane) * 2 + 1] = make_float4(cPrev, cPrev, w, w);
        }

        // coefs for step t from normalized old pointer
        float e = push * (Qp * invs);
        float f = pop  * (Q  * invs);
        float a = 1.0f - e - f;
        float c = 1e-6f * f;

        // sharpened next pointer: (np/sigma)^s via MUFU lg2/ex2
        float Qn = (np > 0.f) ? ex2f(s5 * (lnp - lgs)) : 0.f;

        Q = Qn;
        popPrev = pop; aPrev = a; ePrev = e; cPrev = c;
    }

    // final store for t = 255
    {
        float sig = Q;
#pragma unroll
        for (int o = 16; o; o >>= 1) sig += __shfl_xor_sync(FULL, sig, o);
        float invs = 1.0f / fmaxf(sig, 1e-8f);
        float w = popPrev * Q * invs;
        cb[((TT - 1) * NS + lane) * 2]     = make_float4(aPrev, aPrev, ePrev, ePrev);
        cb[((TT - 1) * NS + lane) * 2 + 1] = make_float4(cPrev, cPrev, w, w);
    }
}

// ---------------------------------------------------------------------------
// K3: stack recurrence, f32x2 packed. 128 threads; thread = (b, cols 2i,2i+1).
// Coefs (pre-duplicated) staged into a 4-slot smem ring via cp.async,
// prefetched 3 steps ahead. Per slot: 2x LDS.128 + 3x FFMA2. One barrier/step.
// ---------------------------------------------------------------------------
__global__ void __launch_bounds__(128) stack_kernel(
    const float* __restrict__ x,
    float* __restrict__ out)
{
    __shared__ ulonglong2 cbuf[4][NS * 2];   // 4 KB ring

    const int b = blockIdx.x;
    const int i = threadIdx.x;

    const ulonglong2* cb  = coef2_buf + (size_t)b * TT * NS * 2;
    const float2*     xb2 = (const float2*)(x + (size_t)b * TT * TD) + i;
    float2*           ob2 = (float2*)(out + (size_t)b * TT * TD) + i;

    unsigned long long st2[NS];
    {
        unsigned long long init;
        PACK2(init, 1e-6f, 1e-6f);
#pragma unroll
        for (int n = 0; n < NS; n++) st2[n] = init;
    }

    // prologue: stages 0..2 in flight (64 x 16B per stage, threads i<64)
    if (i < NS * 2) {
        uint32_t s0 = (uint32_t)__cvta_generic_to_shared(&cbuf[0][i]);
        cp16(s0,                      &cb[0 * NS * 2 + i]); CP_COMMIT();
        cp16(s0 + 1 * NS * 2 * 16,    &cb[1 * NS * 2 + i]); CP_COMMIT();
        cp16(s0 + 2 * NS * 2 * 16,    &cb[2 * NS * 2 + i]); CP_COMMIT();
        CP_WAIT2();                   // stage 0 complete
    }
    __syncthreads();

    float2 xv = __ldg(xb2);           // x for t = 0

    for (int t = 0; t < TT; t++) {
        float2 xnext = (t + 1 < TT) ? __ldg(xb2 + (size_t)(t + 1) * (TD / 2))
                                    : make_float2(0.f, 0.f);

        unsigned long long in2, s2;
        PACK2(in2, xv.x, xv.y);
        PACK2(s2, 0.0f, 0.0f);

        const ulonglong2* cf = cbuf[t & 3];
#pragma unroll
        for (int n = 0; n < NS; n++) {
            ulonglong2 A = cf[2 * n];        // {a,a | e,e}
            ulonglong2 B = cf[2 * n + 1];    // {c,c | w,w}
            unsigned long long z2, v2;
            FMA2(z2, A.y, in2, B.x);         // e*in + c
            FMA2(v2, A.x, st2[n], z2);       // a*st + z
            st2[n] = v2;
            FMA2(s2, v2, B.y, s2);           // s += v*w
        }
        float lo, hi;
        UNPACK2(lo, hi, s2);
        ob2[(size_t)t * (TD / 2)] = make_float2(lo, hi);

        // issue stage t+3 (slot last read at t-1; everyone passed that
        // barrier), then ensure stage t+1 is complete.
        if (i < NS * 2) {
            if (t + 3 < TT) {
                uint32_t sa = (uint32_t)__cvta_generic_to_shared(&cbuf[(t + 3) & 3][i]);
                cp16(sa, &cb[(size_t)(t + 3) * NS * 2 + i]);
            }
            CP_COMMIT();
            CP_WAIT2();
        }
        __syncthreads();
        xv = xnext;
    }
}

// ---------------------------------------------------------------------------
// metadata order: x[B*T*D], should_pop[D], sharpen_pointer[1],
//                 latch_enable[D], latch_init[B*D]  -> out[B*T*D] float32
// ---------------------------------------------------------------------------
extern "C" void kernel_launch(void* const* d_in, const int* in_sizes, int n_in,
                              void* d_out, int out_size)
{
    const float* x   = (const float*)d_in[0];
    const float* sp  = (const float*)d_in[1];
    const float* shp = (const float*)d_in[2];
    const float* le  = (const float*)d_in[3];
    const float* li  = (const float*)d_in[4];
    float* out = (float*)d_out;

    precompute_g_kernel<<<(BB * TT) / 8, 256>>>(x, le);
    latch_pop_kernel<<<BB, 256>>>(x, sp, li);
    pointer_scan_kernel<<<BB, 32>>>(shp);
    stack_kernel<<<BB, 128>>>(x, out);
}